// round 9
// baseline (speedup 1.0000x reference)
#include <cuda_runtime.h>
#include <cuda_fp16.h>
#include <math_constants.h>
#include <cstdint>

#define NB 64
#define NC 64
#define NHW 4096
#define NPTS 262144
#define NK 512
#define MP 128
#define NTILES (NPTS/MP)
#define GRID 148
#define TPB 256

#define OFF_OUT  0
#define OFF_DIFF (NPTS*NC)
#define OFF_IND  (OFF_DIFF + 1)
#define OFF_EMB  (OFF_IND + NPTS)
#define OFF_CS   (OFF_EMB + NC*NK)
#define OFF_EAVG (OFF_CS + NK)

// row pitch 160B (40 words): 8B frag chunks land on 32 distinct banks/phase
#define PITCH 160

// smem offsets (bytes)
#define A_EH   0            // 512*160 = 81920
#define A_EL   81920
#define A_XH   163840       // 128*160 = 20480
#define A_NHN  184320       // 512*4
#define A_NRM2 186368       // 256*4
#define A_NORM 187392       // 128*4
#define A_SK   187904       // 128*4
#define A_RED  188416       // 32
#define A_SMEM 188448

__device__ float g_neghn[NK];
__device__ float g_margc;
__device__ float g_esum[NC*NK];
__device__ float g_counts[NK];
__device__ float g_inv[NK];
__device__ float g_diff;
__device__ int   g_nsusp;
__device__ int   g_susp[NPTS];

// fragment-order permutation of channel c within its 16-block:
// positions 4t..4t+3 hold channels {2t, 2t+1, 2t+8, 2t+9}
__device__ __forceinline__ int permc(int c) {
    int blk = c & ~15, j = c & 15;
    return (j < 8) ? (blk + (j >> 1)*4 + (j & 1))
                   : (blk + ((j - 8) >> 1)*4 + 2 + (j & 1));
}

__device__ __forceinline__ void mma_f16(float* d, const uint32_t* a,
                                        uint32_t b0, uint32_t b1) {
    asm volatile(
        "mma.sync.aligned.m16n8k16.row.col.f32.f16.f16.f32 "
        "{%0,%1,%2,%3}, {%4,%5,%6,%7}, {%8,%9}, {%0,%1,%2,%3};"
        : "+f"(d[0]), "+f"(d[1]), "+f"(d[2]), "+f"(d[3])
        : "r"(a[0]), "r"(a[1]), "r"(a[2]), "r"(a[3]), "r"(b0), "r"(b1));
}

// ---------------------------------------------------------------------------
__global__ void vq_prep(const float* __restrict__ emb) {
    __shared__ float redm[16];
    int gt = blockIdx.x*blockDim.x + threadIdx.x;   // 64 x 512
    if (gt < NC*NK) g_esum[gt] = 0.f;
    if (blockIdx.x != 0) return;
    int k = threadIdx.x;
    g_counts[k] = 0.f;
    if (k == 0) { g_diff = 0.f; g_nsusp = 0; }
    float s = 0.f;
    #pragma unroll 8
    for (int c = 0; c < NC; c++) { float v = emb[c*NK + k]; s = fmaf(v, v, s); }
    g_neghn[k] = -0.5f*s;
    float m = s;
    #pragma unroll
    for (int o = 16; o; o >>= 1) m = fmaxf(m, __shfl_down_sync(0xffffffffu, m, o));
    if ((k & 31) == 0) redm[k >> 5] = m;
    __syncthreads();
    if (k == 0) {
        float mm = 0.f;
        #pragma unroll
        for (int w = 0; w < 16; w++) mm = fmaxf(mm, redm[w]);
        g_margc = (6.0f/4096.0f)*sqrtf(mm);
    }
}

// ---------------------------------------------------------------------------
// Scores via mma.sync fp16 2-term (xh*eh + xh*el); certified argmax;
// gather reconstructed from smem; diff; scatter via REDG.
// ---------------------------------------------------------------------------
__global__ __launch_bounds__(TPB, 1) void vq_scores(
    const float* __restrict__ input, const float* __restrict__ emb,
    float* __restrict__ out, float* __restrict__ ind_out)
{
    extern __shared__ char sma[];
    float* nhn  = (float*)(sma + A_NHN);
    float* nrm2 = (float*)(sma + A_NRM2);
    float* norm = (float*)(sma + A_NORM);
    int*   sk   = (int*)  (sma + A_SK);
    float* red  = (float*)(sma + A_RED);

    const int tid = threadIdx.x;
    const int wid = tid >> 5;
    const int lid = tid & 31;
    const int gid = lid >> 2;
    const int tig = lid & 3;

    // Stage E hi/lo (rows = code n, permuted channel cols)
    for (int i = tid; i < NK*NC/4; i += TPB) {
        int c  = i >> 7;
        int k4 = (i & 127)*4;
        float4 v = *(const float4*)&emb[c*NK + k4];
        float vv[4] = {v.x, v.y, v.z, v.w};
        int pc = permc(c);
        #pragma unroll
        for (int j = 0; j < 4; j++) {
            __half h = __float2half_rn(vv[j]);
            __half l = __float2half_rn(vv[j] - __half2float(h));
            *(__half*)(sma + A_EH + (k4 + j)*PITCH + pc*2) = h;
            *(__half*)(sma + A_EL + (k4 + j)*PITCH + pc*2) = l;
        }
    }
    for (int i = tid; i < NK; i += TPB) nhn[i] = g_neghn[i];
    const float margc = g_margc;

    float ddiff = 0.f;

    for (int t = blockIdx.x; t < NTILES; t += gridDim.x) {
        const int n0tile = t*MP;
        const int b      = n0tile >> 12;
        const int hw0    = n0tile & 4095;
        const float* xin = input + (size_t)b*NC*NHW + hw0;
        float*       op  = out   + (size_t)b*NC*NHW + hw0;

        __syncthreads();   // prior tile fully consumed

        // stage X hi (rows = point, permuted channel cols) + norm partials
        {
            const int p = tid & 127;
            float nsum = 0.f;
            #pragma unroll 8
            for (int j = 0; j < 32; j++) {
                int c = (tid >> 7) + 2*j;
                float v = xin[c*NHW + p];
                *(__half*)(sma + A_XH + p*PITCH + permc(c)*2) = __float2half_rn(v);
                nsum = fmaf(v, v, nsum);
            }
            nrm2[tid] = nsum;
        }
        __syncthreads();
        if (tid < MP) norm[tid] = nrm2[tid] + nrm2[tid + 128];
        __syncthreads();

        // A fragments (xh only): rows r0 = wid*16+gid, r1 = r0+8
        const int r0 = wid*16 + gid;
        const int r1 = r0 + 8;
        uint32_t ah[4][4];
        #pragma unroll
        for (int ks = 0; ks < 4; ks++) {
            uint2 v0 = *(const uint2*)(sma + A_XH + r0*PITCH + ks*32 + tig*8);
            uint2 v1 = *(const uint2*)(sma + A_XH + r1*PITCH + ks*32 + tig*8);
            ah[ks][0] = v0.x; ah[ks][1] = v1.x;  // a0, a1
            ah[ks][2] = v0.y; ah[ks][3] = v1.y;  // a2, a3
        }

        float b1lo = -CUDART_INF_F, b2lo = -CUDART_INF_F;
        float b1hi = -CUDART_INF_F, b2hi = -CUDART_INF_F;
        int   i1lo = 0, i1hi = 0;

        #pragma unroll 1
        for (int ch = 0; ch < 8; ch++) {
            const int n0 = ch*64;
            float acc[8][4];
            #pragma unroll
            for (int nt = 0; nt < 8; nt++)
                acc[nt][0] = acc[nt][1] = acc[nt][2] = acc[nt][3] = 0.f;

            #pragma unroll
            for (int nt = 0; nt < 8; nt++) {
                const int n = n0 + nt*8 + gid;
                #pragma unroll
                for (int ks = 0; ks < 4; ks++) {
                    uint2 bh = *(const uint2*)(sma + A_EH + n*PITCH + ks*32 + tig*8);
                    uint2 bl = *(const uint2*)(sma + A_EL + n*PITCH + ks*32 + tig*8);
                    mma_f16(acc[nt], ah[ks], bh.x, bh.y);   // xh*eh
                    mma_f16(acc[nt], ah[ks], bl.x, bl.y);   // xh*el
                }
            }

            #pragma unroll
            for (int nt = 0; nt < 8; nt++) {
                int code0 = n0 + nt*8 + tig*2;
                float nh0 = nhn[code0], nh1 = nhn[code0 + 1];
                float v0 = acc[nt][0] + nh0;
                float v1 = acc[nt][1] + nh1;
                float v2 = acc[nt][2] + nh0;
                float v3 = acc[nt][3] + nh1;
                if (v0 > b1lo) { b2lo = b1lo; b1lo = v0; i1lo = code0; }
                else           { b2lo = fmaxf(b2lo, v0); }
                if (v1 > b1lo) { b2lo = b1lo; b1lo = v1; i1lo = code0 + 1; }
                else           { b2lo = fmaxf(b2lo, v1); }
                if (v2 > b1hi) { b2hi = b1hi; b1hi = v2; i1hi = code0; }
                else           { b2hi = fmaxf(b2hi, v2); }
                if (v3 > b1hi) { b2hi = b1hi; b1hi = v3; i1hi = code0 + 1; }
                else           { b2hi = fmaxf(b2hi, v3); }
            }
        }

        // reduce across the 4 lanes sharing each row
        #pragma unroll
        for (int o = 1; o <= 2; o <<= 1) {
            float ob1 = __shfl_xor_sync(0xffffffffu, b1lo, o);
            int   oi1 = __shfl_xor_sync(0xffffffffu, i1lo, o);
            float ob2 = __shfl_xor_sync(0xffffffffu, b2lo, o);
            if (ob1 > b1lo || (ob1 == b1lo && oi1 < i1lo)) {
                b2lo = fmaxf(b1lo, ob2); b1lo = ob1; i1lo = oi1;
            } else b2lo = fmaxf(b2lo, ob1);
            ob1 = __shfl_xor_sync(0xffffffffu, b1hi, o);
            oi1 = __shfl_xor_sync(0xffffffffu, i1hi, o);
            ob2 = __shfl_xor_sync(0xffffffffu, b2hi, o);
            if (ob1 > b1hi || (ob1 == b1hi && oi1 < i1hi)) {
                b2hi = fmaxf(b1hi, ob2); b1hi = ob1; i1hi = oi1;
            } else b2hi = fmaxf(b2hi, ob1);
        }

        if (tig == 0) {
            #pragma unroll
            for (int h = 0; h < 2; h++) {
                int   p  = h ? r1 : r0;
                float B1 = h ? b1hi : b1lo;
                float B2 = h ? b2hi : b2lo;
                int   I1 = h ? i1hi : i1lo;
                sk[p] = I1;
                ind_out[n0tile + p] = (float)I1;
                atomicAdd(&g_counts[I1], 1.f);
                float marg = fmaf(margc, sqrtf(norm[p]), 1e-4f);
                if (B1 - B2 <= marg) {
                    int s = atomicAdd(&g_nsusp, 1);
                    g_susp[s] = n0tile + p;
                }
            }
        }
        __syncthreads();

        // gather q from smem (eh+el), out store, diff, REDG scatter
        for (int i = tid; i < NC*MP; i += TPB) {
            int c = i >> 7;
            int p = i & 127;
            int k = sk[p];
            int pc = permc(c);
            float q = __half2float(*(const __half*)(sma + A_EH + k*PITCH + pc*2))
                    + __half2float(*(const __half*)(sma + A_EL + k*PITCH + pc*2));
            float xv = xin[c*NHW + p];
            op[c*NHW + p] = q;
            float d = q - xv;
            ddiff = fmaf(d, d, ddiff);
            atomicAdd(&g_esum[c*NK + k], xv);
        }
    }

    #pragma unroll
    for (int o = 16; o; o >>= 1) ddiff += __shfl_down_sync(0xffffffffu, ddiff, o);
    if (lid == 0) red[wid] = ddiff;
    __syncthreads();
    if (tid == 0) {
        float s = 0.f;
        #pragma unroll
        for (int w = 0; w < 8; w++) s += red[w];
        atomicAdd(&g_diff, s);
    }
}

// ---------------------------------------------------------------------------
// exact fp32 rescore for suspect points; patch out/ind/diff/esum/counts
// ---------------------------------------------------------------------------
__global__ __launch_bounds__(TPB) void vq_rescue(
    const float* __restrict__ input, const float* __restrict__ emb,
    float* __restrict__ out)
{
    const int lid = threadIdx.x & 31;
    const int gw  = blockIdx.x*(TPB/32) + (threadIdx.x >> 5);
    const int nw  = gridDim.x*(TPB/32);
    const int ns  = g_nsusp;

    for (int s = gw; s < ns; s += nw) {
        int n  = g_susp[s];
        int b  = n >> 12;
        int hw = n & 4095;
        const float* xp = input + (size_t)b*NC*NHW + hw;
        float x[NC];
        #pragma unroll 8
        for (int c = 0; c < NC; c++) x[c] = __ldg(&xp[c*NHW]);

        float best = -CUDART_INF_F;
        int   bk   = NK;
        for (int k = lid; k < NK; k += 32) {
            float sc = g_neghn[k];
            #pragma unroll 8
            for (int c = 0; c < NC; c++) sc = fmaf(x[c], __ldg(&emb[c*NK + k]), sc);
            if (sc > best) { best = sc; bk = k; }
        }
        #pragma unroll
        for (int o = 16; o; o >>= 1) {
            float ov = __shfl_down_sync(0xffffffffu, best, o);
            int   oi = __shfl_down_sync(0xffffffffu, bk, o);
            if (ov > best || (ov == best && oi < bk)) { best = ov; bk = oi; }
        }
        bk = __shfl_sync(0xffffffffu, bk, 0);

        int oldk = (int)out[OFF_IND + n];
        // always rewrite out with EXACT code values for this point (also fixes
        // the 2^-22 reconstruction error on suspects); patch stats if flipped
        float dd = 0.f;
        for (int c = lid; c < NC; c += 32) {
            float qn = __ldg(&emb[c*NK + bk]);
            float qo = __ldg(&emb[c*NK + oldk]);
            float xv = x[c];
            out[OFF_OUT + (size_t)b*NC*NHW + c*NHW + hw] = qn;
            if (bk != oldk) {
                dd += (qn - xv)*(qn - xv) - (qo - xv)*(qo - xv);
                atomicAdd(&g_esum[c*NK + oldk], -xv);
                atomicAdd(&g_esum[c*NK + bk],    xv);
            }
        }
        if (bk != oldk) {
            #pragma unroll
            for (int o = 16; o; o >>= 1) dd += __shfl_down_sync(0xffffffffu, dd, o);
            if (lid == 0) {
                atomicAdd(&g_diff, dd);
                atomicAdd(&g_counts[oldk], -1.f);
                atomicAdd(&g_counts[bk],    1.f);
                out[OFF_IND + n] = (float)bk;
            }
        }
    }
}

// ---------------------------------------------------------------------------
__global__ void vq_csum(const float* __restrict__ cs, float* __restrict__ d_out) {
    __shared__ float red[16];
    int k = threadIdx.x;  // 512
    float ncs = fmaf(cs[k], 0.99f, 0.01f*g_counts[k]);
    d_out[OFF_CS + k] = ncs;
    float v = ncs;
    #pragma unroll
    for (int o = 16; o; o >>= 1) v += __shfl_down_sync(0xffffffffu, v, o);
    if ((k & 31) == 0) red[k >> 5] = v;
    __syncthreads();
    if (k < 32) {
        float w = (k < 16) ? red[k] : 0.f;
        #pragma unroll
        for (int o = 8; o; o >>= 1) w += __shfl_down_sync(0xffffffffu, w, o);
        if (k == 0) red[0] = w;
    }
    __syncthreads();
    float tot = red[0];
    float csk = (ncs + 1e-5f) / (tot + 512.f*1e-5f) * tot;
    g_inv[k] = 1.f/csk;
    if (k == 0) d_out[OFF_DIFF] = g_diff * (1.f/(float)(NPTS*NC));
}

__global__ void vq_ema(const float* __restrict__ eavg, float* __restrict__ d_out) {
    int i = blockIdx.x*blockDim.x + threadIdx.x;   // 32768
    float na = fmaf(eavg[i], 0.99f, 0.01f*g_esum[i]);
    d_out[OFF_EAVG + i] = na;
    d_out[OFF_EMB  + i] = na * g_inv[i & 511];
}

// ---------------------------------------------------------------------------
extern "C" void kernel_launch(void* const* d_in, const int* in_sizes, int n_in,
                              void* d_out, int out_size) {
    const float* input = (const float*)d_in[0];
    const float* emb   = (const float*)d_in[1];
    const float* cs    = (const float*)d_in[2];
    const float* eavg  = (const float*)d_in[3];
    float* out = (float*)d_out;

    cudaFuncSetAttribute(vq_scores, cudaFuncAttributeMaxDynamicSharedMemorySize, A_SMEM);

    vq_prep<<<64, 512>>>(emb);
    vq_scores<<<GRID, TPB, A_SMEM>>>(input, emb, out + OFF_OUT, out + OFF_IND);
    vq_rescue<<<GRID, TPB>>>(input, emb, out);
    vq_csum<<<1, NK>>>(cs, out);
    vq_ema<<<NC*NK/TPB, TPB>>>(eavg, out);
}

// round 11
// speedup vs baseline: 1.0046x; 1.0046x over previous
#include <cuda_runtime.h>
#include <cuda_fp16.h>
#include <math_constants.h>
#include <cstdint>

#define NB 64
#define NC 64
#define NHW 4096
#define NPTS 262144
#define NK 512
#define MP 128
#define NTILES (NPTS/MP)
#define GRID 148
#define TPB 256

#define OFF_OUT  0
#define OFF_DIFF (NPTS*NC)
#define OFF_IND  (OFF_DIFF + 1)
#define OFF_EMB  (OFF_IND + NPTS)
#define OFF_CS   (OFF_EMB + NC*NK)
#define OFF_EAVG (OFF_CS + NK)

// row pitch 160B (40 words): 8B frag chunks land on 32 distinct banks/phase
#define PITCH 160

// smem offsets (bytes)
#define A_EH   0            // 512*160 = 81920
#define A_EL   81920
#define A_XH   163840       // 128*160 = 20480
#define A_NHN  184320       // 512*4
#define A_NRM2 186368       // 256*4
#define A_NORM 187392       // 128*4
#define A_SK   187904       // 128*4
#define A_RED  188416       // 32
#define A_SMEM 188448

__device__ float g_neghn[NK];
__device__ float g_margc;
__device__ float g_esum[NC*NK];
__device__ float g_counts[NK];
__device__ float g_inv[NK];
__device__ float g_diff;
__device__ int   g_nsusp;
__device__ int   g_susp[NPTS];

// fragment-order permutation of channel c within its 16-block:
// positions 4t..4t+3 hold channels {2t, 2t+1, 2t+8, 2t+9}
__device__ __forceinline__ int permc(int c) {
    int blk = c & ~15, j = c & 15;
    return (j < 8) ? (blk + (j >> 1)*4 + (j & 1))
                   : (blk + ((j - 8) >> 1)*4 + 2 + (j & 1));
}

__device__ __forceinline__ void mma_f16(float* d, const uint32_t* a,
                                        uint32_t b0, uint32_t b1) {
    asm volatile(
        "mma.sync.aligned.m16n8k16.row.col.f32.f16.f16.f32 "
        "{%0,%1,%2,%3}, {%4,%5,%6,%7}, {%8,%9}, {%0,%1,%2,%3};"
        : "+f"(d[0]), "+f"(d[1]), "+f"(d[2]), "+f"(d[3])
        : "r"(a[0]), "r"(a[1]), "r"(a[2]), "r"(a[3]), "r"(b0), "r"(b1));
}

// ---------------------------------------------------------------------------
__global__ void vq_prep(const float* __restrict__ emb) {
    __shared__ float redm[16];
    int gt = blockIdx.x*blockDim.x + threadIdx.x;   // 64 x 512
    if (gt < NC*NK) g_esum[gt] = 0.f;
    if (blockIdx.x != 0) return;
    int k = threadIdx.x;
    g_counts[k] = 0.f;
    if (k == 0) { g_diff = 0.f; g_nsusp = 0; }
    float s = 0.f;
    #pragma unroll 8
    for (int c = 0; c < NC; c++) { float v = emb[c*NK + k]; s = fmaf(v, v, s); }
    g_neghn[k] = -0.5f*s;
    float m = s;
    #pragma unroll
    for (int o = 16; o; o >>= 1) m = fmaxf(m, __shfl_down_sync(0xffffffffu, m, o));
    if ((k & 31) == 0) redm[k >> 5] = m;
    __syncthreads();
    if (k == 0) {
        float mm = 0.f;
        #pragma unroll
        for (int w = 0; w < 16; w++) mm = fmaxf(mm, redm[w]);
        g_margc = (6.0f/4096.0f)*sqrtf(mm);
    }
}

// ---------------------------------------------------------------------------
// Scores via mma.sync fp16 2-term (xh*eh + xh*el); certified argmax;
// gather reconstructed from smem; diff; scatter via REDG.
// ---------------------------------------------------------------------------
__global__ __launch_bounds__(TPB, 1) void vq_scores(
    const float* __restrict__ input, const float* __restrict__ emb,
    float* __restrict__ out, float* __restrict__ ind_out)
{
    extern __shared__ char sma[];
    float* nhn  = (float*)(sma + A_NHN);
    float* nrm2 = (float*)(sma + A_NRM2);
    float* norm = (float*)(sma + A_NORM);
    int*   sk   = (int*)  (sma + A_SK);
    float* red  = (float*)(sma + A_RED);

    const int tid = threadIdx.x;
    const int wid = tid >> 5;
    const int lid = tid & 31;
    const int gid = lid >> 2;
    const int tig = lid & 3;

    // Stage E hi/lo (rows = code n, permuted channel cols)
    for (int i = tid; i < NK*NC/4; i += TPB) {
        int c  = i >> 7;
        int k4 = (i & 127)*4;
        float4 v = *(const float4*)&emb[c*NK + k4];
        float vv[4] = {v.x, v.y, v.z, v.w};
        int pc = permc(c);
        #pragma unroll
        for (int j = 0; j < 4; j++) {
            __half h = __float2half_rn(vv[j]);
            __half l = __float2half_rn(vv[j] - __half2float(h));
            *(__half*)(sma + A_EH + (k4 + j)*PITCH + pc*2) = h;
            *(__half*)(sma + A_EL + (k4 + j)*PITCH + pc*2) = l;
        }
    }
    for (int i = tid; i < NK; i += TPB) nhn[i] = g_neghn[i];
    const float margc = g_margc;

    float ddiff = 0.f;

    for (int t = blockIdx.x; t < NTILES; t += gridDim.x) {
        const int n0tile = t*MP;
        const int b      = n0tile >> 12;
        const int hw0    = n0tile & 4095;
        const float* xin = input + (size_t)b*NC*NHW + hw0;
        float*       op  = out   + (size_t)b*NC*NHW + hw0;

        __syncthreads();   // prior tile fully consumed

        // stage X hi (rows = point, permuted channel cols) + norm partials
        {
            const int p = tid & 127;
            float nsum = 0.f;
            #pragma unroll 8
            for (int j = 0; j < 32; j++) {
                int c = (tid >> 7) + 2*j;
                float v = xin[c*NHW + p];
                *(__half*)(sma + A_XH + p*PITCH + permc(c)*2) = __float2half_rn(v);
                nsum = fmaf(v, v, nsum);
            }
            nrm2[tid] = nsum;
        }
        __syncthreads();
        if (tid < MP) norm[tid] = nrm2[tid] + nrm2[tid + 128];
        __syncthreads();

        // A fragments (xh only): rows r0 = wid*16+gid, r1 = r0+8
        const int r0 = wid*16 + gid;
        const int r1 = r0 + 8;
        uint32_t ah[4][4];
        #pragma unroll
        for (int ks = 0; ks < 4; ks++) {
            uint2 v0 = *(const uint2*)(sma + A_XH + r0*PITCH + ks*32 + tig*8);
            uint2 v1 = *(const uint2*)(sma + A_XH + r1*PITCH + ks*32 + tig*8);
            ah[ks][0] = v0.x; ah[ks][1] = v1.x;  // a0, a1
            ah[ks][2] = v0.y; ah[ks][3] = v1.y;  // a2, a3
        }

        float b1lo = -CUDART_INF_F, b2lo = -CUDART_INF_F;
        float b1hi = -CUDART_INF_F, b2hi = -CUDART_INF_F;
        int   i1lo = 0, i1hi = 0;

        #pragma unroll 1
        for (int ch = 0; ch < 8; ch++) {
            const int n0 = ch*64;
            float acc[8][4];
            #pragma unroll
            for (int nt = 0; nt < 8; nt++)
                acc[nt][0] = acc[nt][1] = acc[nt][2] = acc[nt][3] = 0.f;

            #pragma unroll
            for (int nt = 0; nt < 8; nt++) {
                const int n = n0 + nt*8 + gid;
                #pragma unroll
                for (int ks = 0; ks < 4; ks++) {
                    uint2 bh = *(const uint2*)(sma + A_EH + n*PITCH + ks*32 + tig*8);
                    uint2 bl = *(const uint2*)(sma + A_EL + n*PITCH + ks*32 + tig*8);
                    mma_f16(acc[nt], ah[ks], bh.x, bh.y);   // xh*eh
                    mma_f16(acc[nt], ah[ks], bl.x, bl.y);   // xh*el
                }
            }

            #pragma unroll
            for (int nt = 0; nt < 8; nt++) {
                int code0 = n0 + nt*8 + tig*2;
                float nh0 = nhn[code0], nh1 = nhn[code0 + 1];
                float v0 = acc[nt][0] + nh0;
                float v1 = acc[nt][1] + nh1;
                float v2 = acc[nt][2] + nh0;
                float v3 = acc[nt][3] + nh1;
                if (v0 > b1lo) { b2lo = b1lo; b1lo = v0; i1lo = code0; }
                else           { b2lo = fmaxf(b2lo, v0); }
                if (v1 > b1lo) { b2lo = b1lo; b1lo = v1; i1lo = code0 + 1; }
                else           { b2lo = fmaxf(b2lo, v1); }
                if (v2 > b1hi) { b2hi = b1hi; b1hi = v2; i1hi = code0; }
                else           { b2hi = fmaxf(b2hi, v2); }
                if (v3 > b1hi) { b2hi = b1hi; b1hi = v3; i1hi = code0 + 1; }
                else           { b2hi = fmaxf(b2hi, v3); }
            }
        }

        // reduce across the 4 lanes sharing each row
        #pragma unroll
        for (int o = 1; o <= 2; o <<= 1) {
            float ob1 = __shfl_xor_sync(0xffffffffu, b1lo, o);
            int   oi1 = __shfl_xor_sync(0xffffffffu, i1lo, o);
            float ob2 = __shfl_xor_sync(0xffffffffu, b2lo, o);
            if (ob1 > b1lo || (ob1 == b1lo && oi1 < i1lo)) {
                b2lo = fmaxf(b1lo, ob2); b1lo = ob1; i1lo = oi1;
            } else b2lo = fmaxf(b2lo, ob1);
            ob1 = __shfl_xor_sync(0xffffffffu, b1hi, o);
            oi1 = __shfl_xor_sync(0xffffffffu, i1hi, o);
            ob2 = __shfl_xor_sync(0xffffffffu, b2hi, o);
            if (ob1 > b1hi || (ob1 == b1hi && oi1 < i1hi)) {
                b2hi = fmaxf(b1hi, ob2); b1hi = ob1; i1hi = oi1;
            } else b2hi = fmaxf(b2hi, ob1);
        }

        if (tig == 0) {
            #pragma unroll
            for (int h = 0; h < 2; h++) {
                int   p  = h ? r1 : r0;
                float B1 = h ? b1hi : b1lo;
                float B2 = h ? b2hi : b2lo;
                int   I1 = h ? i1hi : i1lo;
                sk[p] = I1;
                ind_out[n0tile + p] = (float)I1;
                atomicAdd(&g_counts[I1], 1.f);
                float marg = fmaf(margc, sqrtf(norm[p]), 1e-4f);
                if (B1 - B2 <= marg) {
                    int s = atomicAdd(&g_nsusp, 1);
                    g_susp[s] = n0tile + p;
                }
            }
        }
        __syncthreads();

        // gather q from smem (eh+el), out store, diff, REDG scatter
        for (int i = tid; i < NC*MP; i += TPB) {
            int c = i >> 7;
            int p = i & 127;
            int k = sk[p];
            int pc = permc(c);
            float q = __half2float(*(const __half*)(sma + A_EH + k*PITCH + pc*2))
                    + __half2float(*(const __half*)(sma + A_EL + k*PITCH + pc*2));
            float xv = xin[c*NHW + p];
            op[c*NHW + p] = q;
            float d = q - xv;
            ddiff = fmaf(d, d, ddiff);
            atomicAdd(&g_esum[c*NK + k], xv);
        }
    }

    #pragma unroll
    for (int o = 16; o; o >>= 1) ddiff += __shfl_down_sync(0xffffffffu, ddiff, o);
    if (lid == 0) red[wid] = ddiff;
    __syncthreads();
    if (tid == 0) {
        float s = 0.f;
        #pragma unroll
        for (int w = 0; w < 8; w++) s += red[w];
        atomicAdd(&g_diff, s);
    }
}

// ---------------------------------------------------------------------------
// exact fp32 rescore for suspect points; patch out/ind/diff/esum/counts
// ---------------------------------------------------------------------------
__global__ __launch_bounds__(TPB) void vq_rescue(
    const float* __restrict__ input, const float* __restrict__ emb,
    float* __restrict__ out)
{
    const int lid = threadIdx.x & 31;
    const int gw  = blockIdx.x*(TPB/32) + (threadIdx.x >> 5);
    const int nw  = gridDim.x*(TPB/32);
    const int ns  = g_nsusp;

    for (int s = gw; s < ns; s += nw) {
        int n  = g_susp[s];
        int b  = n >> 12;
        int hw = n & 4095;
        const float* xp = input + (size_t)b*NC*NHW + hw;
        float x[NC];
        #pragma unroll 8
        for (int c = 0; c < NC; c++) x[c] = __ldg(&xp[c*NHW]);

        float best = -CUDART_INF_F;
        int   bk   = NK;
        for (int k = lid; k < NK; k += 32) {
            float sc = g_neghn[k];
            #pragma unroll 8
            for (int c = 0; c < NC; c++) sc = fmaf(x[c], __ldg(&emb[c*NK + k]), sc);
            if (sc > best) { best = sc; bk = k; }
        }
        #pragma unroll
        for (int o = 16; o; o >>= 1) {
            float ov = __shfl_down_sync(0xffffffffu, best, o);
            int   oi = __shfl_down_sync(0xffffffffu, bk, o);
            if (ov > best || (ov == best && oi < bk)) { best = ov; bk = oi; }
        }
        bk = __shfl_sync(0xffffffffu, bk, 0);

        int oldk = (int)out[OFF_IND + n];
        // always rewrite out with EXACT code values for this point (also fixes
        // the 2^-22 reconstruction error on suspects); patch stats if flipped
        float dd = 0.f;
        for (int c = lid; c < NC; c += 32) {
            float qn = __ldg(&emb[c*NK + bk]);
            float qo = __ldg(&emb[c*NK + oldk]);
            float xv = x[c];
            out[OFF_OUT + (size_t)b*NC*NHW + c*NHW + hw] = qn;
            if (bk != oldk) {
                dd += (qn - xv)*(qn - xv) - (qo - xv)*(qo - xv);
                atomicAdd(&g_esum[c*NK + oldk], -xv);
                atomicAdd(&g_esum[c*NK + bk],    xv);
            }
        }
        if (bk != oldk) {
            #pragma unroll
            for (int o = 16; o; o >>= 1) dd += __shfl_down_sync(0xffffffffu, dd, o);
            if (lid == 0) {
                atomicAdd(&g_diff, dd);
                atomicAdd(&g_counts[oldk], -1.f);
                atomicAdd(&g_counts[bk],    1.f);
                out[OFF_IND + n] = (float)bk;
            }
        }
    }
}

// ---------------------------------------------------------------------------
__global__ void vq_csum(const float* __restrict__ cs, float* __restrict__ d_out) {
    __shared__ float red[16];
    int k = threadIdx.x;  // 512
    float ncs = fmaf(cs[k], 0.99f, 0.01f*g_counts[k]);
    d_out[OFF_CS + k] = ncs;
    float v = ncs;
    #pragma unroll
    for (int o = 16; o; o >>= 1) v += __shfl_down_sync(0xffffffffu, v, o);
    if ((k & 31) == 0) red[k >> 5] = v;
    __syncthreads();
    if (k < 32) {
        float w = (k < 16) ? red[k] : 0.f;
        #pragma unroll
        for (int o = 8; o; o >>= 1) w += __shfl_down_sync(0xffffffffu, w, o);
        if (k == 0) red[0] = w;
    }
    __syncthreads();
    float tot = red[0];
    float csk = (ncs + 1e-5f) / (tot + 512.f*1e-5f) * tot;
    g_inv[k] = 1.f/csk;
    if (k == 0) d_out[OFF_DIFF] = g_diff * (1.f/(float)(NPTS*NC));
}

__global__ void vq_ema(const float* __restrict__ eavg, float* __restrict__ d_out) {
    int i = blockIdx.x*blockDim.x + threadIdx.x;   // 32768
    float na = fmaf(eavg[i], 0.99f, 0.01f*g_esum[i]);
    d_out[OFF_EAVG + i] = na;
    d_out[OFF_EMB  + i] = na * g_inv[i & 511];
}

// ---------------------------------------------------------------------------
extern "C" void kernel_launch(void* const* d_in, const int* in_sizes, int n_in,
                              void* d_out, int out_size) {
    const float* input = (const float*)d_in[0];
    const float* emb   = (const float*)d_in[1];
    const float* cs    = (const float*)d_in[2];
    const float* eavg  = (const float*)d_in[3];
    float* out = (float*)d_out;

    cudaFuncSetAttribute(vq_scores, cudaFuncAttributeMaxDynamicSharedMemorySize, A_SMEM);

    vq_prep<<<64, 512>>>(emb);
    vq_scores<<<GRID, TPB, A_SMEM>>>(input, emb, out + OFF_OUT, out + OFF_IND);
    vq_rescue<<<GRID, TPB>>>(input, emb, out);
    vq_csum<<<1, NK>>>(cs, out);
    vq_ema<<<NC*NK/TPB, TPB>>>(eavg, out);
}

// round 12
// speedup vs baseline: 1.0100x; 1.0054x over previous
#include <cuda_runtime.h>
#include <cuda_fp16.h>
#include <math_constants.h>
#include <cstdint>

#define NB 64
#define NC 64
#define NHW 4096
#define NPTS 262144
#define NK 512
#define MP 128
#define NTILES (NPTS/MP)
#define GRID 148
#define TPB 256

#define OFF_OUT  0
#define OFF_DIFF (NPTS*NC)
#define OFF_IND  (OFF_DIFF + 1)
#define OFF_EMB  (OFF_IND + NPTS)
#define OFF_CS   (OFF_EMB + NC*NK)
#define OFF_EAVG (OFF_CS + NK)

// row pitch 160B (40 words): 8B frag chunks land on 32 distinct banks/phase
#define PITCH 160

// smem offsets (bytes)
#define A_EH   0            // 512*160 = 81920
#define A_EL   81920
#define A_XH   163840       // 128*160 = 20480
#define A_NHN  184320       // 512*4
#define A_NRM2 186368       // 256*4
#define A_NORM 187392       // 128*4
#define A_SK   187904       // 128*4
#define A_RED  188416       // 32
#define A_SMEM 188448

__device__ float g_neghn[NK];
__device__ float g_margc;
__device__ float g_esum[NC*NK];
__device__ float g_counts[NK];
__device__ float g_inv[NK];
__device__ float g_diff;
__device__ int   g_nsusp;
__device__ int   g_susp[NPTS];

// fragment-order permutation of channel c within its 16-block:
// positions 4t..4t+3 hold channels {2t, 2t+1, 2t+8, 2t+9}
__device__ __forceinline__ int permc(int c) {
    int blk = c & ~15, j = c & 15;
    return (j < 8) ? (blk + (j >> 1)*4 + (j & 1))
                   : (blk + ((j - 8) >> 1)*4 + 2 + (j & 1));
}

__device__ __forceinline__ void mma_f16(float* d, const uint32_t* a,
                                        uint32_t b0, uint32_t b1) {
    asm volatile(
        "mma.sync.aligned.m16n8k16.row.col.f32.f16.f16.f32 "
        "{%0,%1,%2,%3}, {%4,%5,%6,%7}, {%8,%9}, {%0,%1,%2,%3};"
        : "+f"(d[0]), "+f"(d[1]), "+f"(d[2]), "+f"(d[3])
        : "r"(a[0]), "r"(a[1]), "r"(a[2]), "r"(a[3]), "r"(b0), "r"(b1));
}

// ---------------------------------------------------------------------------
__global__ void vq_prep(const float* __restrict__ emb) {
    __shared__ float redm[16];
    int gt = blockIdx.x*blockDim.x + threadIdx.x;   // 64 x 512
    if (gt < NC*NK) g_esum[gt] = 0.f;
    if (blockIdx.x != 0) return;
    int k = threadIdx.x;
    g_counts[k] = 0.f;
    if (k == 0) { g_diff = 0.f; g_nsusp = 0; }
    float s = 0.f;
    #pragma unroll 8
    for (int c = 0; c < NC; c++) { float v = emb[c*NK + k]; s = fmaf(v, v, s); }
    g_neghn[k] = -0.5f*s;
    float m = s;
    #pragma unroll
    for (int o = 16; o; o >>= 1) m = fmaxf(m, __shfl_down_sync(0xffffffffu, m, o));
    if ((k & 31) == 0) redm[k >> 5] = m;
    __syncthreads();
    if (k == 0) {
        float mm = 0.f;
        #pragma unroll
        for (int w = 0; w < 16; w++) mm = fmaxf(mm, redm[w]);
        g_margc = (6.0f/4096.0f)*sqrtf(mm);
    }
}

// ---------------------------------------------------------------------------
// Scores via mma.sync fp16 2-term (xh*eh + xh*el); certified argmax;
// gather reconstructed from smem; diff; scatter via REDG.
// ---------------------------------------------------------------------------
__global__ __launch_bounds__(TPB, 1) void vq_scores(
    const float* __restrict__ input, const float* __restrict__ emb,
    float* __restrict__ out, float* __restrict__ ind_out)
{
    extern __shared__ char sma[];
    float* nhn  = (float*)(sma + A_NHN);
    float* nrm2 = (float*)(sma + A_NRM2);
    float* norm = (float*)(sma + A_NORM);
    int*   sk   = (int*)  (sma + A_SK);
    float* red  = (float*)(sma + A_RED);

    const int tid = threadIdx.x;
    const int wid = tid >> 5;
    const int lid = tid & 31;
    const int gid = lid >> 2;
    const int tig = lid & 3;

    // Stage E hi/lo (rows = code n, permuted channel cols)
    for (int i = tid; i < NK*NC/4; i += TPB) {
        int c  = i >> 7;
        int k4 = (i & 127)*4;
        float4 v = *(const float4*)&emb[c*NK + k4];
        float vv[4] = {v.x, v.y, v.z, v.w};
        int pc = permc(c);
        #pragma unroll
        for (int j = 0; j < 4; j++) {
            __half h = __float2half_rn(vv[j]);
            __half l = __float2half_rn(vv[j] - __half2float(h));
            *(__half*)(sma + A_EH + (k4 + j)*PITCH + pc*2) = h;
            *(__half*)(sma + A_EL + (k4 + j)*PITCH + pc*2) = l;
        }
    }
    for (int i = tid; i < NK; i += TPB) nhn[i] = g_neghn[i];
    const float margc = g_margc;

    float ddiff = 0.f;

    for (int t = blockIdx.x; t < NTILES; t += gridDim.x) {
        const int n0tile = t*MP;
        const int b      = n0tile >> 12;
        const int hw0    = n0tile & 4095;
        const float* xin = input + (size_t)b*NC*NHW + hw0;
        float*       op  = out   + (size_t)b*NC*NHW + hw0;

        __syncthreads();   // prior tile fully consumed

        // stage X hi (rows = point, permuted channel cols) + norm partials
        {
            const int p = tid & 127;
            float nsum = 0.f;
            #pragma unroll 8
            for (int j = 0; j < 32; j++) {
                int c = (tid >> 7) + 2*j;
                float v = xin[c*NHW + p];
                *(__half*)(sma + A_XH + p*PITCH + permc(c)*2) = __float2half_rn(v);
                nsum = fmaf(v, v, nsum);
            }
            nrm2[tid] = nsum;
        }
        __syncthreads();
        if (tid < MP) norm[tid] = nrm2[tid] + nrm2[tid + 128];
        __syncthreads();

        // A fragments (xh only): rows r0 = wid*16+gid, r1 = r0+8
        const int r0 = wid*16 + gid;
        const int r1 = r0 + 8;
        uint32_t ah[4][4];
        #pragma unroll
        for (int ks = 0; ks < 4; ks++) {
            uint2 v0 = *(const uint2*)(sma + A_XH + r0*PITCH + ks*32 + tig*8);
            uint2 v1 = *(const uint2*)(sma + A_XH + r1*PITCH + ks*32 + tig*8);
            ah[ks][0] = v0.x; ah[ks][1] = v1.x;  // a0, a1
            ah[ks][2] = v0.y; ah[ks][3] = v1.y;  // a2, a3
        }

        float b1lo = -CUDART_INF_F, b2lo = -CUDART_INF_F;
        float b1hi = -CUDART_INF_F, b2hi = -CUDART_INF_F;
        int   i1lo = 0, i1hi = 0;

        #pragma unroll 1
        for (int ch = 0; ch < 8; ch++) {
            const int n0 = ch*64;
            float acc[8][4];
            #pragma unroll
            for (int nt = 0; nt < 8; nt++)
                acc[nt][0] = acc[nt][1] = acc[nt][2] = acc[nt][3] = 0.f;

            #pragma unroll
            for (int nt = 0; nt < 8; nt++) {
                const int n = n0 + nt*8 + gid;
                #pragma unroll
                for (int ks = 0; ks < 4; ks++) {
                    uint2 bh = *(const uint2*)(sma + A_EH + n*PITCH + ks*32 + tig*8);
                    uint2 bl = *(const uint2*)(sma + A_EL + n*PITCH + ks*32 + tig*8);
                    mma_f16(acc[nt], ah[ks], bh.x, bh.y);   // xh*eh
                    mma_f16(acc[nt], ah[ks], bl.x, bl.y);   // xh*el
                }
            }

            #pragma unroll
            for (int nt = 0; nt < 8; nt++) {
                int code0 = n0 + nt*8 + tig*2;
                float nh0 = nhn[code0], nh1 = nhn[code0 + 1];
                float v0 = acc[nt][0] + nh0;
                float v1 = acc[nt][1] + nh1;
                float v2 = acc[nt][2] + nh0;
                float v3 = acc[nt][3] + nh1;
                if (v0 > b1lo) { b2lo = b1lo; b1lo = v0; i1lo = code0; }
                else           { b2lo = fmaxf(b2lo, v0); }
                if (v1 > b1lo) { b2lo = b1lo; b1lo = v1; i1lo = code0 + 1; }
                else           { b2lo = fmaxf(b2lo, v1); }
                if (v2 > b1hi) { b2hi = b1hi; b1hi = v2; i1hi = code0; }
                else           { b2hi = fmaxf(b2hi, v2); }
                if (v3 > b1hi) { b2hi = b1hi; b1hi = v3; i1hi = code0 + 1; }
                else           { b2hi = fmaxf(b2hi, v3); }
            }
        }

        // reduce across the 4 lanes sharing each row
        #pragma unroll
        for (int o = 1; o <= 2; o <<= 1) {
            float ob1 = __shfl_xor_sync(0xffffffffu, b1lo, o);
            int   oi1 = __shfl_xor_sync(0xffffffffu, i1lo, o);
            float ob2 = __shfl_xor_sync(0xffffffffu, b2lo, o);
            if (ob1 > b1lo || (ob1 == b1lo && oi1 < i1lo)) {
                b2lo = fmaxf(b1lo, ob2); b1lo = ob1; i1lo = oi1;
            } else b2lo = fmaxf(b2lo, ob1);
            ob1 = __shfl_xor_sync(0xffffffffu, b1hi, o);
            oi1 = __shfl_xor_sync(0xffffffffu, i1hi, o);
            ob2 = __shfl_xor_sync(0xffffffffu, b2hi, o);
            if (ob1 > b1hi || (ob1 == b1hi && oi1 < i1hi)) {
                b2hi = fmaxf(b1hi, ob2); b1hi = ob1; i1hi = oi1;
            } else b2hi = fmaxf(b2hi, ob1);
        }

        if (tig == 0) {
            #pragma unroll
            for (int h = 0; h < 2; h++) {
                int   p  = h ? r1 : r0;
                float B1 = h ? b1hi : b1lo;
                float B2 = h ? b2hi : b2lo;
                int   I1 = h ? i1hi : i1lo;
                sk[p] = I1;
                ind_out[n0tile + p] = (float)I1;
                atomicAdd(&g_counts[I1], 1.f);
                float marg = fmaf(margc, sqrtf(norm[p]), 1e-4f);
                if (B1 - B2 <= marg) {
                    int s = atomicAdd(&g_nsusp, 1);
                    g_susp[s] = n0tile + p;
                }
            }
        }
        __syncthreads();

        // gather q from smem (eh+el), out store, diff, REDG scatter
        for (int i = tid; i < NC*MP; i += TPB) {
            int c = i >> 7;
            int p = i & 127;
            int k = sk[p];
            int pc = permc(c);
            float q = __half2float(*(const __half*)(sma + A_EH + k*PITCH + pc*2))
                    + __half2float(*(const __half*)(sma + A_EL + k*PITCH + pc*2));
            float xv = xin[c*NHW + p];
            op[c*NHW + p] = q;
            float d = q - xv;
            ddiff = fmaf(d, d, ddiff);
            atomicAdd(&g_esum[c*NK + k], xv);
        }
    }

    #pragma unroll
    for (int o = 16; o; o >>= 1) ddiff += __shfl_down_sync(0xffffffffu, ddiff, o);
    if (lid == 0) red[wid] = ddiff;
    __syncthreads();
    if (tid == 0) {
        float s = 0.f;
        #pragma unroll
        for (int w = 0; w < 8; w++) s += red[w];
        atomicAdd(&g_diff, s);
    }
}

// ---------------------------------------------------------------------------
// exact fp32 rescore for suspect points; patch out/ind/diff/esum/counts
// ---------------------------------------------------------------------------
__global__ __launch_bounds__(TPB) void vq_rescue(
    const float* __restrict__ input, const float* __restrict__ emb,
    float* __restrict__ out)
{
    const int lid = threadIdx.x & 31;
    const int gw  = blockIdx.x*(TPB/32) + (threadIdx.x >> 5);
    const int nw  = gridDim.x*(TPB/32);
    const int ns  = g_nsusp;

    for (int s = gw; s < ns; s += nw) {
        int n  = g_susp[s];
        int b  = n >> 12;
        int hw = n & 4095;
        const float* xp = input + (size_t)b*NC*NHW + hw;
        float x[NC];
        #pragma unroll 8
        for (int c = 0; c < NC; c++) x[c] = __ldg(&xp[c*NHW]);

        float best = -CUDART_INF_F;
        int   bk   = NK;
        for (int k = lid; k < NK; k += 32) {
            float sc = g_neghn[k];
            #pragma unroll 8
            for (int c = 0; c < NC; c++) sc = fmaf(x[c], __ldg(&emb[c*NK + k]), sc);
            if (sc > best) { best = sc; bk = k; }
        }
        #pragma unroll
        for (int o = 16; o; o >>= 1) {
            float ov = __shfl_down_sync(0xffffffffu, best, o);
            int   oi = __shfl_down_sync(0xffffffffu, bk, o);
            if (ov > best || (ov == best && oi < bk)) { best = ov; bk = oi; }
        }
        bk = __shfl_sync(0xffffffffu, bk, 0);

        int oldk = (int)out[OFF_IND + n];
        // always rewrite out with EXACT code values for this point (also fixes
        // the 2^-22 reconstruction error on suspects); patch stats if flipped
        float dd = 0.f;
        for (int c = lid; c < NC; c += 32) {
            float qn = __ldg(&emb[c*NK + bk]);
            float qo = __ldg(&emb[c*NK + oldk]);
            float xv = x[c];
            out[OFF_OUT + (size_t)b*NC*NHW + c*NHW + hw] = qn;
            if (bk != oldk) {
                dd += (qn - xv)*(qn - xv) - (qo - xv)*(qo - xv);
                atomicAdd(&g_esum[c*NK + oldk], -xv);
                atomicAdd(&g_esum[c*NK + bk],    xv);
            }
        }
        if (bk != oldk) {
            #pragma unroll
            for (int o = 16; o; o >>= 1) dd += __shfl_down_sync(0xffffffffu, dd, o);
            if (lid == 0) {
                atomicAdd(&g_diff, dd);
                atomicAdd(&g_counts[oldk], -1.f);
                atomicAdd(&g_counts[bk],    1.f);
                out[OFF_IND + n] = (float)bk;
            }
        }
    }
}

// ---------------------------------------------------------------------------
__global__ void vq_csum(const float* __restrict__ cs, float* __restrict__ d_out) {
    __shared__ float red[16];
    int k = threadIdx.x;  // 512
    float ncs = fmaf(cs[k], 0.99f, 0.01f*g_counts[k]);
    d_out[OFF_CS + k] = ncs;
    float v = ncs;
    #pragma unroll
    for (int o = 16; o; o >>= 1) v += __shfl_down_sync(0xffffffffu, v, o);
    if ((k & 31) == 0) red[k >> 5] = v;
    __syncthreads();
    if (k < 32) {
        float w = (k < 16) ? red[k] : 0.f;
        #pragma unroll
        for (int o = 8; o; o >>= 1) w += __shfl_down_sync(0xffffffffu, w, o);
        if (k == 0) red[0] = w;
    }
    __syncthreads();
    float tot = red[0];
    float csk = (ncs + 1e-5f) / (tot + 512.f*1e-5f) * tot;
    g_inv[k] = 1.f/csk;
    if (k == 0) d_out[OFF_DIFF] = g_diff * (1.f/(float)(NPTS*NC));
}

__global__ void vq_ema(const float* __restrict__ eavg, float* __restrict__ d_out) {
    int i = blockIdx.x*blockDim.x + threadIdx.x;   // 32768
    float na = fmaf(eavg[i], 0.99f, 0.01f*g_esum[i]);
    d_out[OFF_EAVG + i] = na;
    d_out[OFF_EMB  + i] = na * g_inv[i & 511];
}

// ---------------------------------------------------------------------------
extern "C" void kernel_launch(void* const* d_in, const int* in_sizes, int n_in,
                              void* d_out, int out_size) {
    const float* input = (const float*)d_in[0];
    const float* emb   = (const float*)d_in[1];
    const float* cs    = (const float*)d_in[2];
    const float* eavg  = (const float*)d_in[3];
    float* out = (float*)d_out;

    cudaFuncSetAttribute(vq_scores, cudaFuncAttributeMaxDynamicSharedMemorySize, A_SMEM);

    vq_prep<<<64, 512>>>(emb);
    vq_scores<<<GRID, TPB, A_SMEM>>>(input, emb, out + OFF_OUT, out + OFF_IND);
    vq_rescue<<<GRID, TPB>>>(input, emb, out);
    vq_csum<<<1, NK>>>(cs, out);
    vq_ema<<<NC*NK/TPB, TPB>>>(eavg, out);
}

// round 13
// speedup vs baseline: 1.8973x; 1.8785x over previous
#include <cuda_runtime.h>
#include <cuda_bf16.h>
#include <math_constants.h>
#include <cstdint>

#define NB 64
#define NC 64
#define NHW 4096
#define NPTS 262144
#define NK 512
#define MP 128
#define NTILES (NPTS/MP)
#define GRID 148
#define TPB 256

#define OFF_OUT  0
#define OFF_DIFF (NPTS*NC)
#define OFF_IND  (OFF_DIFF + 1)
#define OFF_EMB  (OFF_IND + NPTS)
#define OFF_CS   (OFF_EMB + NC*NK)
#define OFF_EAVG (OFF_CS + NK)

// row pitch 160B (40 words): 8B frag chunks land on 32 distinct banks/phase
#define PITCH 160

// smem offsets (bytes)
#define A_EH   0            // 512*160 = 81920
#define A_EL   81920        // 81920
#define A_XH   163840       // 128*160 = 20480
#define A_XL   184320       // 20480
#define A_NHN  204800       // 2048
#define A_NRM2 206848       // 1024
#define A_NORM 207872       // 512
#define A_SK   208384       // 512
#define A_RED  208896       // 32
#define A_SMEM 208928

__device__ float g_neghn[NK];
__device__ float g_margc;
__device__ float g_esum[NC*NK];
__device__ float g_counts[NK];
__device__ float g_inv[NK];
__device__ float g_diff;
__device__ int   g_nsusp;
__device__ int   g_susp[NPTS];

// fragment-order permutation of channel c within its 16-block:
// positions 4t..4t+3 hold channels {2t, 2t+1, 2t+8, 2t+9}
__device__ __forceinline__ int permc(int c) {
    int blk = c & ~15, j = c & 15;
    return (j < 8) ? (blk + (j >> 1)*4 + (j & 1))
                   : (blk + ((j - 8) >> 1)*4 + 2 + (j & 1));
}

__device__ __forceinline__ void mma_bf16(float* d, const uint32_t* a,
                                         uint32_t b0, uint32_t b1) {
    asm volatile(
        "mma.sync.aligned.m16n8k16.row.col.f32.bf16.bf16.f32 "
        "{%0,%1,%2,%3}, {%4,%5,%6,%7}, {%8,%9}, {%0,%1,%2,%3};"
        : "+f"(d[0]), "+f"(d[1]), "+f"(d[2]), "+f"(d[3])
        : "r"(a[0]), "r"(a[1]), "r"(a[2]), "r"(a[3]), "r"(b0), "r"(b1));
}

// ---------------------------------------------------------------------------
__global__ void vq_prep(const float* __restrict__ emb) {
    __shared__ float redm[16];
    int gt = blockIdx.x*blockDim.x + threadIdx.x;   // 64 x 512
    if (gt < NC*NK) g_esum[gt] = 0.f;
    if (blockIdx.x != 0) return;
    int k = threadIdx.x;
    g_counts[k] = 0.f;
    if (k == 0) { g_diff = 0.f; g_nsusp = 0; }
    float s = 0.f;
    #pragma unroll 8
    for (int c = 0; c < NC; c++) { float v = emb[c*NK + k]; s = fmaf(v, v, s); }
    g_neghn[k] = -0.5f*s;
    float m = s;
    #pragma unroll
    for (int o = 16; o; o >>= 1) m = fmaxf(m, __shfl_down_sync(0xffffffffu, m, o));
    if ((k & 31) == 0) redm[k >> 5] = m;
    __syncthreads();
    if (k == 0) {
        float mm = 0.f;
        #pragma unroll
        for (int w = 0; w < 16; w++) mm = fmaxf(mm, redm[w]);
        g_margc = (8.0f/65536.0f)*sqrtf(mm);
    }
}

// ---------------------------------------------------------------------------
// Scores via mma.sync bf16 3-term (xh*eh + xh*el + xl*eh); certified argmax;
// gather reconstructed from smem; diff; scatter via REDG.
// ---------------------------------------------------------------------------
__global__ __launch_bounds__(TPB, 1) void vq_scores(
    const float* __restrict__ input, const float* __restrict__ emb,
    float* __restrict__ out, float* __restrict__ ind_out)
{
    extern __shared__ char sma[];
    float* nhn  = (float*)(sma + A_NHN);
    float* nrm2 = (float*)(sma + A_NRM2);
    float* norm = (float*)(sma + A_NORM);
    int*   sk   = (int*)  (sma + A_SK);
    float* red  = (float*)(sma + A_RED);

    const int tid = threadIdx.x;
    const int wid = tid >> 5;
    const int lid = tid & 31;
    const int gid = lid >> 2;
    const int tig = lid & 3;

    // Stage E hi/lo (rows = code n, permuted channel cols)
    for (int i = tid; i < NK*NC/4; i += TPB) {
        int c  = i >> 7;
        int k4 = (i & 127)*4;
        float4 v = *(const float4*)&emb[c*NK + k4];
        float vv[4] = {v.x, v.y, v.z, v.w};
        int pc = permc(c);
        #pragma unroll
        for (int j = 0; j < 4; j++) {
            __nv_bfloat16 h = __float2bfloat16(vv[j]);
            __nv_bfloat16 l = __float2bfloat16(vv[j] - __bfloat162float(h));
            *(__nv_bfloat16*)(sma + A_EH + (k4 + j)*PITCH + pc*2) = h;
            *(__nv_bfloat16*)(sma + A_EL + (k4 + j)*PITCH + pc*2) = l;
        }
    }
    for (int i = tid; i < NK; i += TPB) nhn[i] = g_neghn[i];
    const float margc = g_margc;

    float ddiff = 0.f;

    for (int t = blockIdx.x; t < NTILES; t += gridDim.x) {
        const int n0tile = t*MP;
        const int b      = n0tile >> 12;
        const int hw0    = n0tile & 4095;
        const float* xin = input + (size_t)b*NC*NHW + hw0;
        float*       op  = out   + (size_t)b*NC*NHW + hw0;

        __syncthreads();   // prior tile fully consumed

        // stage X hi/lo (rows = point, permuted channel cols) + norm partials
        {
            const int p = tid & 127;
            float nsum = 0.f;
            #pragma unroll 8
            for (int j = 0; j < 32; j++) {
                int c = (tid >> 7) + 2*j;
                float v = xin[c*NHW + p];
                __nv_bfloat16 h = __float2bfloat16(v);
                __nv_bfloat16 l = __float2bfloat16(v - __bfloat162float(h));
                int pc = permc(c);
                *(__nv_bfloat16*)(sma + A_XH + p*PITCH + pc*2) = h;
                *(__nv_bfloat16*)(sma + A_XL + p*PITCH + pc*2) = l;
                nsum = fmaf(v, v, nsum);
            }
            nrm2[tid] = nsum;
        }
        __syncthreads();
        if (tid < MP) norm[tid] = nrm2[tid] + nrm2[tid + 128];
        __syncthreads();

        // A fragments: rows r0 = wid*16+gid, r1 = r0+8 (hi and lo)
        const int r0 = wid*16 + gid;
        const int r1 = r0 + 8;
        uint32_t ah[4][4], al[4][4];
        #pragma unroll
        for (int ks = 0; ks < 4; ks++) {
            uint2 h0 = *(const uint2*)(sma + A_XH + r0*PITCH + ks*32 + tig*8);
            uint2 h1 = *(const uint2*)(sma + A_XH + r1*PITCH + ks*32 + tig*8);
            uint2 l0 = *(const uint2*)(sma + A_XL + r0*PITCH + ks*32 + tig*8);
            uint2 l1 = *(const uint2*)(sma + A_XL + r1*PITCH + ks*32 + tig*8);
            ah[ks][0] = h0.x; ah[ks][1] = h1.x; ah[ks][2] = h0.y; ah[ks][3] = h1.y;
            al[ks][0] = l0.x; al[ks][1] = l1.x; al[ks][2] = l0.y; al[ks][3] = l1.y;
        }

        float b1lo = -CUDART_INF_F, b2lo = -CUDART_INF_F;
        float b1hi = -CUDART_INF_F, b2hi = -CUDART_INF_F;
        int   i1lo = 0, i1hi = 0;

        #pragma unroll 1
        for (int ch = 0; ch < 8; ch++) {
            const int n0 = ch*64;
            float acc[8][4];
            #pragma unroll
            for (int nt = 0; nt < 8; nt++)
                acc[nt][0] = acc[nt][1] = acc[nt][2] = acc[nt][3] = 0.f;

            #pragma unroll
            for (int nt = 0; nt < 8; nt++) {
                const int n = n0 + nt*8 + gid;
                #pragma unroll
                for (int ks = 0; ks < 4; ks++) {
                    uint2 bh = *(const uint2*)(sma + A_EH + n*PITCH + ks*32 + tig*8);
                    uint2 bl = *(const uint2*)(sma + A_EL + n*PITCH + ks*32 + tig*8);
                    mma_bf16(acc[nt], ah[ks], bh.x, bh.y);   // xh*eh
                    mma_bf16(acc[nt], ah[ks], bl.x, bl.y);   // xh*el
                    mma_bf16(acc[nt], al[ks], bh.x, bh.y);   // xl*eh
                }
            }

            #pragma unroll
            for (int nt = 0; nt < 8; nt++) {
                int code0 = n0 + nt*8 + tig*2;
                float nh0 = nhn[code0], nh1 = nhn[code0 + 1];
                float v0 = acc[nt][0] + nh0;
                float v1 = acc[nt][1] + nh1;
                float v2 = acc[nt][2] + nh0;
                float v3 = acc[nt][3] + nh1;
                if (v0 > b1lo) { b2lo = b1lo; b1lo = v0; i1lo = code0; }
                else           { b2lo = fmaxf(b2lo, v0); }
                if (v1 > b1lo) { b2lo = b1lo; b1lo = v1; i1lo = code0 + 1; }
                else           { b2lo = fmaxf(b2lo, v1); }
                if (v2 > b1hi) { b2hi = b1hi; b1hi = v2; i1hi = code0; }
                else           { b2hi = fmaxf(b2hi, v2); }
                if (v3 > b1hi) { b2hi = b1hi; b1hi = v3; i1hi = code0 + 1; }
                else           { b2hi = fmaxf(b2hi, v3); }
            }
        }

        // reduce across the 4 lanes sharing each row
        #pragma unroll
        for (int o = 1; o <= 2; o <<= 1) {
            float ob1 = __shfl_xor_sync(0xffffffffu, b1lo, o);
            int   oi1 = __shfl_xor_sync(0xffffffffu, i1lo, o);
            float ob2 = __shfl_xor_sync(0xffffffffu, b2lo, o);
            if (ob1 > b1lo || (ob1 == b1lo && oi1 < i1lo)) {
                b2lo = fmaxf(b1lo, ob2); b1lo = ob1; i1lo = oi1;
            } else b2lo = fmaxf(b2lo, ob1);
            ob1 = __shfl_xor_sync(0xffffffffu, b1hi, o);
            oi1 = __shfl_xor_sync(0xffffffffu, i1hi, o);
            ob2 = __shfl_xor_sync(0xffffffffu, b2hi, o);
            if (ob1 > b1hi || (ob1 == b1hi && oi1 < i1hi)) {
                b2hi = fmaxf(b1hi, ob2); b1hi = ob1; i1hi = oi1;
            } else b2hi = fmaxf(b2hi, ob1);
        }

        if (tig == 0) {
            #pragma unroll
            for (int h = 0; h < 2; h++) {
                int   p  = h ? r1 : r0;
                float B1 = h ? b1hi : b1lo;
                float B2 = h ? b2hi : b2lo;
                int   I1 = h ? i1hi : i1lo;
                sk[p] = I1;
                ind_out[n0tile + p] = (float)I1;
                atomicAdd(&g_counts[I1], 1.f);
                float marg = fmaf(margc, sqrtf(norm[p]), 1e-4f);
                if (B1 - B2 <= marg) {
                    int s = atomicAdd(&g_nsusp, 1);
                    g_susp[s] = n0tile + p;
                }
            }
        }
        __syncthreads();

        // gather q from smem (eh+el), out store, diff, REDG scatter
        for (int i = tid; i < NC*MP; i += TPB) {
            int c = i >> 7;
            int p = i & 127;
            int k = sk[p];
            int pc = permc(c);
            float q = __bfloat162float(*(const __nv_bfloat16*)(sma + A_EH + k*PITCH + pc*2))
                    + __bfloat162float(*(const __nv_bfloat16*)(sma + A_EL + k*PITCH + pc*2));
            float xv = xin[c*NHW + p];
            op[c*NHW + p] = q;
            float d = q - xv;
            ddiff = fmaf(d, d, ddiff);
            atomicAdd(&g_esum[c*NK + k], xv);
        }
    }

    #pragma unroll
    for (int o = 16; o; o >>= 1) ddiff += __shfl_down_sync(0xffffffffu, ddiff, o);
    if (lid == 0) red[wid] = ddiff;
    __syncthreads();
    if (tid == 0) {
        float s = 0.f;
        #pragma unroll
        for (int w = 0; w < 8; w++) s += red[w];
        atomicAdd(&g_diff, s);
    }
}

// ---------------------------------------------------------------------------
// exact fp32 rescore for suspect points; patch out/ind/diff/esum/counts
// ---------------------------------------------------------------------------
__global__ __launch_bounds__(TPB) void vq_rescue(
    const float* __restrict__ input, const float* __restrict__ emb,
    float* __restrict__ out)
{
    const int lid = threadIdx.x & 31;
    const int gw  = blockIdx.x*(TPB/32) + (threadIdx.x >> 5);
    const int nw  = gridDim.x*(TPB/32);
    const int ns  = g_nsusp;

    for (int s = gw; s < ns; s += nw) {
        int n  = g_susp[s];
        int b  = n >> 12;
        int hw = n & 4095;
        const float* xp = input + (size_t)b*NC*NHW + hw;
        float x[NC];
        #pragma unroll 8
        for (int c = 0; c < NC; c++) x[c] = __ldg(&xp[c*NHW]);

        float best = -CUDART_INF_F;
        int   bk   = NK;
        for (int k = lid; k < NK; k += 32) {
            float sc = g_neghn[k];
            #pragma unroll 8
            for (int c = 0; c < NC; c++) sc = fmaf(x[c], __ldg(&emb[c*NK + k]), sc);
            if (sc > best) { best = sc; bk = k; }
        }
        #pragma unroll
        for (int o = 16; o; o >>= 1) {
            float ov = __shfl_down_sync(0xffffffffu, best, o);
            int   oi = __shfl_down_sync(0xffffffffu, bk, o);
            if (ov > best || (ov == best && oi < bk)) { best = ov; bk = oi; }
        }
        bk = __shfl_sync(0xffffffffu, bk, 0);

        int oldk = (int)out[OFF_IND + n];
        if (bk != oldk) {
            float dd = 0.f;
            for (int c = lid; c < NC; c += 32) {
                float qn = __ldg(&emb[c*NK + bk]);
                float qo = __ldg(&emb[c*NK + oldk]);
                float xv = x[c];
                out[OFF_OUT + (size_t)b*NC*NHW + c*NHW + hw] = qn;
                dd += (qn - xv)*(qn - xv) - (qo - xv)*(qo - xv);
                atomicAdd(&g_esum[c*NK + oldk], -xv);
                atomicAdd(&g_esum[c*NK + bk],    xv);
            }
            #pragma unroll
            for (int o = 16; o; o >>= 1) dd += __shfl_down_sync(0xffffffffu, dd, o);
            if (lid == 0) {
                atomicAdd(&g_diff, dd);
                atomicAdd(&g_counts[oldk], -1.f);
                atomicAdd(&g_counts[bk],    1.f);
                out[OFF_IND + n] = (float)bk;
            }
        }
    }
}

// ---------------------------------------------------------------------------
__global__ void vq_csum(const float* __restrict__ cs, float* __restrict__ d_out) {
    __shared__ float red[16];
    int k = threadIdx.x;  // 512
    float ncs = fmaf(cs[k], 0.99f, 0.01f*g_counts[k]);
    d_out[OFF_CS + k] = ncs;
    float v = ncs;
    #pragma unroll
    for (int o = 16; o; o >>= 1) v += __shfl_down_sync(0xffffffffu, v, o);
    if ((k & 31) == 0) red[k >> 5] = v;
    __syncthreads();
    if (k < 32) {
        float w = (k < 16) ? red[k] : 0.f;
        #pragma unroll
        for (int o = 8; o; o >>= 1) w += __shfl_down_sync(0xffffffffu, w, o);
        if (k == 0) red[0] = w;
    }
    __syncthreads();
    float tot = red[0];
    float csk = (ncs + 1e-5f) / (tot + 512.f*1e-5f) * tot;
    g_inv[k] = 1.f/csk;
    if (k == 0) d_out[OFF_DIFF] = g_diff * (1.f/(float)(NPTS*NC));
}

__global__ void vq_ema(const float* __restrict__ eavg, float* __restrict__ d_out) {
    int i = blockIdx.x*blockDim.x + threadIdx.x;   // 32768
    float na = fmaf(eavg[i], 0.99f, 0.01f*g_esum[i]);
    d_out[OFF_EAVG + i] = na;
    d_out[OFF_EMB  + i] = na * g_inv[i & 511];
}

// ---------------------------------------------------------------------------
extern "C" void kernel_launch(void* const* d_in, const int* in_sizes, int n_in,
                              void* d_out, int out_size) {
    const float* input = (const float*)d_in[0];
    const float* emb   = (const float*)d_in[1];
    const float* cs    = (const float*)d_in[2];
    const float* eavg  = (const float*)d_in[3];
    float* out = (float*)d_out;

    cudaFuncSetAttribute(vq_scores, cudaFuncAttributeMaxDynamicSharedMemorySize, A_SMEM);

    vq_prep<<<64, 512>>>(emb);
    vq_scores<<<GRID, TPB, A_SMEM>>>(input, emb, out + OFF_OUT, out + OFF_IND);
    vq_rescue<<<GRID, TPB>>>(input, emb, out);
    vq_csum<<<1, NK>>>(cs, out);
    vq_ema<<<NC*NK/TPB, TPB>>>(eavg, out);
}